// round 15
// baseline (speedup 1.0000x reference)
#include <cuda_runtime.h>
#include <cuda_bf16.h>
#include <cstdint>

#define NN 50000
#define EE 800000
#define LN_EPS 1e-5f
#define ST 36

// ===================== static scratch =====================
__device__ int   g_deg[NN];
__device__ int   g_rowptr[NN + 1];
__device__ int   g_cursor[NN];
__device__ int   g_csrsrc[EE];
__device__ float g_invdeg[NN];
__device__ float g_agg0[(size_t)NN * 64];
// tower 0
__device__ float g_bufA[(size_t)NN * 128];
__device__ float g_bufB[(size_t)NN * 128];
__device__ float g_bufC[(size_t)NN * 128];
// tower 1
__device__ float g_bufD[(size_t)NN * 128];
__device__ float g_bufE[(size_t)NN * 128];
__device__ float g_bufF[(size_t)NN * 128];

__device__ __forceinline__ float to_tf32(float x) {
    uint32_t u;
    asm("cvt.rna.tf32.f32 %0, %1;" : "=r"(u) : "f"(x));
    return __uint_as_float(u);
}

__device__ __forceinline__ void mma_tf32(float& d0, float& d1, float& d2, float& d3,
                                         uint32_t a0, uint32_t a1, uint32_t a2, uint32_t a3,
                                         uint32_t b0, uint32_t b1) {
    asm volatile(
        "mma.sync.aligned.m16n8k8.row.col.f32.tf32.tf32.f32 "
        "{%0,%1,%2,%3}, {%4,%5,%6,%7}, {%8,%9}, {%0,%1,%2,%3};"
        : "+f"(d0), "+f"(d1), "+f"(d2), "+f"(d3)
        : "r"(a0), "r"(a1), "r"(a2), "r"(a3), "r"(b0), "r"(b1));
}

// ===================== CSR build =====================
__global__ void k_count(const int* __restrict__ dst, int* __restrict__ deg) {
    int e = blockIdx.x * blockDim.x + threadIdx.x;
    if (e < EE) atomicAdd(&deg[dst[e]], 1);
}

__global__ void k_scan(const int* __restrict__ deg, int* __restrict__ rowptr,
                       int* __restrict__ cursor, float* __restrict__ invdeg) {
    __shared__ int sums[1024];
    const int t = threadIdx.x;
    const int CH = (NN + 1023) / 1024;
    int s = 0;
    #pragma unroll 4
    for (int i = 0; i < CH; ++i) {
        int idx = t * CH + i;
        if (idx < NN) s += deg[idx];
    }
    sums[t] = s;
    __syncthreads();
    for (int off = 1; off < 1024; off <<= 1) {
        int v = 0;
        if (t >= off) v = sums[t - off];
        __syncthreads();
        if (t >= off) sums[t] += v;
        __syncthreads();
    }
    int run = (t == 0) ? 0 : sums[t - 1];
    for (int i = 0; i < CH; ++i) {
        int idx = t * CH + i;
        if (idx < NN) {
            int d = deg[idx];
            rowptr[idx] = run;
            cursor[idx] = run;
            invdeg[idx] = 1.0f / (float)(d > 0 ? d : 1);
            run += d;
        }
    }
    if (t == 1023) rowptr[NN] = run;
}

__global__ void k_scatter(const int* __restrict__ src, const int* __restrict__ dst,
                          int* __restrict__ cursor, int* __restrict__ csrsrc) {
    int e = blockIdx.x * blockDim.x + threadIdx.x;
    if (e < EE) {
        int pos = atomicAdd(&cursor[dst[e]], 1);
        csrsrc[pos] = src[e];
    }
}

// ===================== gather aggregation (R3 form) =====================
template <int D>
__global__ void k_gather(const float* __restrict__ h, float* __restrict__ out,
                         const int* __restrict__ rowptr, const int* __restrict__ csrsrc,
                         const float* __restrict__ invdeg) {
    int gw   = (blockIdx.x * blockDim.x + threadIdx.x) >> 5;
    int lane = threadIdx.x & 31;
    if (gw >= NN) return;
    int s = rowptr[gw], e = rowptr[gw + 1];
    if (D == 128) {
        float4 a0 = make_float4(0, 0, 0, 0), a1 = make_float4(0, 0, 0, 0);
        int j = s;
        for (; j + 1 < e; j += 2) {
            int s0 = csrsrc[j], s1 = csrsrc[j + 1];
            float4 v0 = *(const float4*)(h + (size_t)s0 * 128 + lane * 4);
            float4 v1 = *(const float4*)(h + (size_t)s1 * 128 + lane * 4);
            a0.x += v0.x; a0.y += v0.y; a0.z += v0.z; a0.w += v0.w;
            a1.x += v1.x; a1.y += v1.y; a1.z += v1.z; a1.w += v1.w;
        }
        if (j < e) {
            int s0 = csrsrc[j];
            float4 v0 = *(const float4*)(h + (size_t)s0 * 128 + lane * 4);
            a0.x += v0.x; a0.y += v0.y; a0.z += v0.z; a0.w += v0.w;
        }
        float iv = invdeg[gw];
        float4 r;
        r.x = (a0.x + a1.x) * iv; r.y = (a0.y + a1.y) * iv;
        r.z = (a0.z + a1.z) * iv; r.w = (a0.w + a1.w) * iv;
        *(float4*)(out + (size_t)gw * 128 + lane * 4) = r;
    } else {
        float2 a0 = make_float2(0, 0), a1 = make_float2(0, 0);
        int j = s;
        for (; j + 1 < e; j += 2) {
            int s0 = csrsrc[j], s1 = csrsrc[j + 1];
            float2 v0 = *(const float2*)(h + (size_t)s0 * 64 + lane * 2);
            float2 v1 = *(const float2*)(h + (size_t)s1 * 64 + lane * 2);
            a0.x += v0.x; a0.y += v0.y;
            a1.x += v1.x; a1.y += v1.y;
        }
        if (j < e) {
            int s0 = csrsrc[j];
            float2 v0 = *(const float2*)(h + (size_t)s0 * 64 + lane * 2);
            a0.x += v0.x; a0.y += v0.y;
        }
        float iv = invdeg[gw];
        float2 r;
        r.x = (a0.x + a1.x) * iv; r.y = (a0.y + a1.y) * iv;
        *(float2*)(out + (size_t)gw * 64 + lane * 2) = r;
    }
}

// ===================== tf32 mma dense, register-double-buffered ================
// out = [Agg|Hin]@[Wl|Wr]^T + bl ; if DO_LN: LayerNorm(gamma,beta)+ReLU fused.
// Prefetch chunk c+1's global tiles into registers while chunk c's MMAs run.
template <int DI, int DO, bool DO_LN>
__global__ __launch_bounds__(256) void k_mma(
    const float* __restrict__ Agg, const float* __restrict__ Hin,
    const float* __restrict__ Wl, const float* __restrict__ Wr,
    const float* __restrict__ bl, const float* __restrict__ gamma,
    const float* __restrict__ beta, float* __restrict__ out) {
    constexpr int WN = DO / 2;
    constexpr int NI = WN / 8;
    constexpr int NCH = 2 * DI / 32;     // total k-chunks across both phases
    constexpr int WT  = DO / 32;         // W-tile float4s per thread

    __shared__ float As[128 * ST];
    __shared__ float Ws[DO * ST];
    __shared__ float red[DO_LN ? 128 : 1][4];

    const int tid    = threadIdx.x;
    const int wid    = tid >> 5;
    const int lane   = tid & 31;
    const int g      = lane >> 2;
    const int tig    = lane & 3;
    const int warp_m = wid >> 1;
    const int warp_n = wid & 1;
    const int bm     = blockIdx.x * 128;

    float acc[2][NI][4];
    #pragma unroll
    for (int mi = 0; mi < 2; ++mi)
        #pragma unroll
        for (int ni = 0; ni < NI; ++ni)
            #pragma unroll
            for (int q = 0; q < 4; ++q) acc[mi][ni][q] = 0.f;

    float4 pa[4];
    float4 pw[WT];

    auto load_chunk = [&](int c) {
        const int ph = (c >= DI / 32) ? 1 : 0;
        const float* __restrict__ Asrc = ph ? Hin : Agg;
        const float* __restrict__ Wsrc = ph ? Wr : Wl;
        const int kl = (c - ph * (DI / 32)) * 32;
        #pragma unroll
        for (int i = 0; i < 4; ++i) {
            int flat = tid + i * 256;
            int row = flat >> 3, q = flat & 7;
            int m = bm + row;
            pa[i] = make_float4(0.f, 0.f, 0.f, 0.f);
            if (m < NN) pa[i] = *(const float4*)(Asrc + (size_t)m * DI + kl + q * 4);
        }
        #pragma unroll
        for (int i = 0; i < WT; ++i) {
            int flat = tid + i * 256;
            int row = flat >> 3, q = flat & 7;
            pw[i] = *(const float4*)(Wsrc + (size_t)row * DI + kl + q * 4);
        }
    };

    load_chunk(0);

    #pragma unroll
    for (int c = 0; c < NCH; ++c) {
        // store prefetched tiles (tf32-rounded) to smem
        #pragma unroll
        for (int i = 0; i < 4; ++i) {
            int flat = tid + i * 256;
            int row = flat >> 3, q = flat & 7;
            float4 v = pa[i];
            v.x = to_tf32(v.x); v.y = to_tf32(v.y); v.z = to_tf32(v.z); v.w = to_tf32(v.w);
            *(float4*)(As + row * ST + q * 4) = v;
        }
        #pragma unroll
        for (int i = 0; i < WT; ++i) {
            int flat = tid + i * 256;
            int row = flat >> 3, q = flat & 7;
            float4 v = pw[i];
            v.x = to_tf32(v.x); v.y = to_tf32(v.y); v.z = to_tf32(v.z); v.w = to_tf32(v.w);
            *(float4*)(Ws + row * ST + q * 4) = v;
        }
        __syncthreads();

        // prefetch next chunk while MMAs run
        if (c + 1 < NCH) load_chunk(c + 1);

        #pragma unroll
        for (int kk = 0; kk < 4; ++kk) {
            const int kb = kk * 8;
            uint32_t a[2][4];
            #pragma unroll
            for (int mi = 0; mi < 2; ++mi) {
                int rb = warp_m * 32 + mi * 16;
                a[mi][0] = __float_as_uint(As[(rb + g) * ST + kb + tig]);
                a[mi][1] = __float_as_uint(As[(rb + g + 8) * ST + kb + tig]);
                a[mi][2] = __float_as_uint(As[(rb + g) * ST + kb + tig + 4]);
                a[mi][3] = __float_as_uint(As[(rb + g + 8) * ST + kb + tig + 4]);
            }
            #pragma unroll
            for (int ni = 0; ni < NI; ++ni) {
                int nb = warp_n * WN + ni * 8;
                uint32_t b0 = __float_as_uint(Ws[(nb + g) * ST + kb + tig]);
                uint32_t b1 = __float_as_uint(Ws[(nb + g) * ST + kb + tig + 4]);
                #pragma unroll
                for (int mi = 0; mi < 2; ++mi)
                    mma_tf32(acc[mi][ni][0], acc[mi][ni][1], acc[mi][ni][2], acc[mi][ni][3],
                             a[mi][0], a[mi][1], a[mi][2], a[mi][3], b0, b1);
            }
        }
        __syncthreads();
    }

    // ---- epilogue: + bias ----
    #pragma unroll
    for (int mi = 0; mi < 2; ++mi)
        #pragma unroll
        for (int ni = 0; ni < NI; ++ni) {
            int col = warp_n * WN + ni * 8 + tig * 2;
            float b0 = bl[col], b1 = bl[col + 1];
            acc[mi][ni][0] += b0; acc[mi][ni][1] += b1;
            acc[mi][ni][2] += b0; acc[mi][ni][3] += b1;
        }

    if (DO_LN) {
        #pragma unroll
        for (int mi = 0; mi < 2; ++mi) {
            float s0 = 0.f, q0 = 0.f, s1 = 0.f, q1 = 0.f;
            #pragma unroll
            for (int ni = 0; ni < NI; ++ni) {
                s0 += acc[mi][ni][0] + acc[mi][ni][1];
                q0 += acc[mi][ni][0] * acc[mi][ni][0] + acc[mi][ni][1] * acc[mi][ni][1];
                s1 += acc[mi][ni][2] + acc[mi][ni][3];
                q1 += acc[mi][ni][2] * acc[mi][ni][2] + acc[mi][ni][3] * acc[mi][ni][3];
            }
            s0 += __shfl_xor_sync(0xFFFFFFFF, s0, 1); s0 += __shfl_xor_sync(0xFFFFFFFF, s0, 2);
            q0 += __shfl_xor_sync(0xFFFFFFFF, q0, 1); q0 += __shfl_xor_sync(0xFFFFFFFF, q0, 2);
            s1 += __shfl_xor_sync(0xFFFFFFFF, s1, 1); s1 += __shfl_xor_sync(0xFFFFFFFF, s1, 2);
            q1 += __shfl_xor_sync(0xFFFFFFFF, q1, 1); q1 += __shfl_xor_sync(0xFFFFFFFF, q1, 2);
            if (tig == 0) {
                int row0 = warp_m * 32 + mi * 16 + g;
                red[row0][warp_n * 2 + 0] = s0;
                red[row0][warp_n * 2 + 1] = q0;
                red[row0 + 8][warp_n * 2 + 0] = s1;
                red[row0 + 8][warp_n * 2 + 1] = q1;
            }
        }
        __syncthreads();
        #pragma unroll
        for (int mi = 0; mi < 2; ++mi) {
            int row0 = warp_m * 32 + mi * 16 + g;
            float sA = red[row0][0] + red[row0][2];
            float qA = red[row0][1] + red[row0][3];
            float sB = red[row0 + 8][0] + red[row0 + 8][2];
            float qB = red[row0 + 8][1] + red[row0 + 8][3];
            float m0 = sA * (1.0f / DO);
            float rs0 = rsqrtf(qA * (1.0f / DO) - m0 * m0 + LN_EPS);
            float m1 = sB * (1.0f / DO);
            float rs1 = rsqrtf(qB * (1.0f / DO) - m1 * m1 + LN_EPS);
            #pragma unroll
            for (int ni = 0; ni < NI; ++ni) {
                int col = warp_n * WN + ni * 8 + tig * 2;
                float g0 = gamma[col], g1 = gamma[col + 1];
                float bb0 = beta[col], bb1 = beta[col + 1];
                acc[mi][ni][0] = fmaxf((acc[mi][ni][0] - m0) * rs0 * g0 + bb0, 0.f);
                acc[mi][ni][1] = fmaxf((acc[mi][ni][1] - m0) * rs0 * g1 + bb1, 0.f);
                acc[mi][ni][2] = fmaxf((acc[mi][ni][2] - m1) * rs1 * g0 + bb0, 0.f);
                acc[mi][ni][3] = fmaxf((acc[mi][ni][3] - m1) * rs1 * g1 + bb1, 0.f);
            }
        }
    }

    #pragma unroll
    for (int ni = 0; ni < NI; ++ni) {
        int col = warp_n * WN + ni * 8 + tig * 2;
        #pragma unroll
        for (int mi = 0; mi < 2; ++mi) {
            int r0 = bm + warp_m * 32 + mi * 16 + g;
            if (r0 < NN)
                *(float2*)(out + (size_t)r0 * DO + col) =
                    make_float2(acc[mi][ni][0], acc[mi][ni][1]);
            int r1 = r0 + 8;
            if (r1 < NN)
                *(float2*)(out + (size_t)r1 * DO + col) =
                    make_float2(acc[mi][ni][2], acc[mi][ni][3]);
        }
    }
}

// ===================== host: forked-graph towers =====================
extern "C" void kernel_launch(void* const* d_in, const int* in_sizes, int n_in,
                              void* d_out, int out_size) {
    const float* x   = (const float*)d_in[0];
    const int*   ei  = (const int*)d_in[1];
    const int*   src = ei;
    const int*   dst = ei + EE;

    int *pDeg, *pRow, *pCur, *pCsr;
    float *pInv, *pAgg0, *pA, *pB, *pC, *pD, *pE, *pF;
    cudaGetSymbolAddress((void**)&pDeg, g_deg);
    cudaGetSymbolAddress((void**)&pRow, g_rowptr);
    cudaGetSymbolAddress((void**)&pCur, g_cursor);
    cudaGetSymbolAddress((void**)&pCsr, g_csrsrc);
    cudaGetSymbolAddress((void**)&pInv, g_invdeg);
    cudaGetSymbolAddress((void**)&pAgg0, g_agg0);
    cudaGetSymbolAddress((void**)&pA, g_bufA);
    cudaGetSymbolAddress((void**)&pB, g_bufB);
    cudaGetSymbolAddress((void**)&pC, g_bufC);
    cudaGetSymbolAddress((void**)&pD, g_bufD);
    cudaGetSymbolAddress((void**)&pE, g_bufE);
    cudaGetSymbolAddress((void**)&pF, g_bufF);

    float* h0[2] = {pA, pD};
    float* ag[2] = {pB, pE};
    float* h1[2] = {pC, pF};

    const int EB = (EE + 255) / 256;
    const int GW = (NN * 32 + 255) / 256;
    const int DB = (NN + 127) / 128;

    cudaStream_t s1;
    cudaStreamCreateWithFlags(&s1, cudaStreamNonBlocking);
    cudaEvent_t evRoot, evJoin;
    cudaEventCreateWithFlags(&evRoot, cudaEventDisableTiming);
    cudaEventCreateWithFlags(&evJoin, cudaEventDisableTiming);

    // ---- shared setup chain ----
    cudaMemsetAsync(pDeg, 0, NN * sizeof(int), 0);
    k_count<<<EB, 256>>>(dst, pDeg);
    k_scan<<<1, 1024>>>(pDeg, pRow, pCur, pInv);
    k_scatter<<<EB, 256>>>(src, dst, pCur, pCsr);
    k_gather<64><<<GW, 256>>>(x, pAgg0, pRow, pCsr, pInv);

    // ---- fork ----
    cudaEventRecord(evRoot, 0);
    cudaStreamWaitEvent(s1, evRoot, 0);

    for (int t = 0; t < 2; ++t) {
        cudaStream_t st = (t == 0) ? (cudaStream_t)0 : s1;
        const int o = 2 + t * 13;
        const float* Wl0 = (const float*)d_in[o + 0];
        const float* bl0 = (const float*)d_in[o + 1];
        const float* Wr0 = (const float*)d_in[o + 2];
        const float* g0  = (const float*)d_in[o + 3];
        const float* b0  = (const float*)d_in[o + 4];
        const float* Wl1 = (const float*)d_in[o + 5];
        const float* bl1 = (const float*)d_in[o + 6];
        const float* Wr1 = (const float*)d_in[o + 7];
        const float* g1  = (const float*)d_in[o + 8];
        const float* b1  = (const float*)d_in[o + 9];
        const float* Wl2 = (const float*)d_in[o + 10];
        const float* bl2 = (const float*)d_in[o + 11];
        const float* Wr2 = (const float*)d_in[o + 12];
        float* outT = (float*)d_out + (size_t)t * NN * 64;

        // layer 0: GEMM + fused LN+ReLU
        k_mma<64, 128, true><<<DB, 256, 0, st>>>(pAgg0, x, Wl0, Wr0, bl0, g0, b0, h0[t]);
        // layer 1
        k_gather<128><<<GW, 256, 0, st>>>(h0[t], ag[t], pRow, pCsr, pInv);
        k_mma<128, 128, true><<<DB, 256, 0, st>>>(ag[t], h0[t], Wl1, Wr1, bl1, g1, b1, h1[t]);
        // layer 2 (no LN)
        k_gather<128><<<GW, 256, 0, st>>>(h1[t], ag[t], pRow, pCsr, pInv);
        k_mma<128, 64, false><<<DB, 256, 0, st>>>(ag[t], h1[t], Wl2, Wr2, bl2,
                                                  nullptr, nullptr, outT);
    }

    // ---- join ----
    cudaEventRecord(evJoin, s1);
    cudaStreamWaitEvent((cudaStream_t)0, evJoin, 0);
}

// round 16
// speedup vs baseline: 1.0043x; 1.0043x over previous
#include <cuda_runtime.h>
#include <cuda_bf16.h>
#include <cstdint>

#define NN 50000
#define EE 800000
#define LN_EPS 1e-5f
#define ST 36

// ===================== static scratch =====================
__device__ int   g_deg[NN];
__device__ int   g_rowptr[NN + 1];
__device__ int   g_cursor[NN];
__device__ int   g_csrsrc[EE];
__device__ float g_invdeg[NN];
__device__ float g_agg0[(size_t)NN * 64];
// tower 0
__device__ float g_bufA[(size_t)NN * 128];
__device__ float g_bufB[(size_t)NN * 128];
__device__ float g_bufC[(size_t)NN * 128];
// tower 1
__device__ float g_bufD[(size_t)NN * 128];
__device__ float g_bufE[(size_t)NN * 128];
__device__ float g_bufF[(size_t)NN * 128];

__device__ __forceinline__ float to_tf32(float x) {
    uint32_t u;
    asm("cvt.rna.tf32.f32 %0, %1;" : "=r"(u) : "f"(x));
    return __uint_as_float(u);
}

__device__ __forceinline__ void mma_tf32(float& d0, float& d1, float& d2, float& d3,
                                         uint32_t a0, uint32_t a1, uint32_t a2, uint32_t a3,
                                         uint32_t b0, uint32_t b1) {
    asm volatile(
        "mma.sync.aligned.m16n8k8.row.col.f32.tf32.tf32.f32 "
        "{%0,%1,%2,%3}, {%4,%5,%6,%7}, {%8,%9}, {%0,%1,%2,%3};"
        : "+f"(d0), "+f"(d1), "+f"(d2), "+f"(d3)
        : "r"(a0), "r"(a1), "r"(a2), "r"(a3), "r"(b0), "r"(b1));
}

// ===================== CSR build =====================
__global__ void k_count(const int* __restrict__ dst, int* __restrict__ deg) {
    int e = blockIdx.x * blockDim.x + threadIdx.x;
    if (e < EE) atomicAdd(&deg[dst[e]], 1);
}

__global__ void k_scan(const int* __restrict__ deg, int* __restrict__ rowptr,
                       int* __restrict__ cursor, float* __restrict__ invdeg) {
    __shared__ int sums[1024];
    const int t = threadIdx.x;
    const int CH = (NN + 1023) / 1024;
    int s = 0;
    #pragma unroll 4
    for (int i = 0; i < CH; ++i) {
        int idx = t * CH + i;
        if (idx < NN) s += deg[idx];
    }
    sums[t] = s;
    __syncthreads();
    for (int off = 1; off < 1024; off <<= 1) {
        int v = 0;
        if (t >= off) v = sums[t - off];
        __syncthreads();
        if (t >= off) sums[t] += v;
        __syncthreads();
    }
    int run = (t == 0) ? 0 : sums[t - 1];
    for (int i = 0; i < CH; ++i) {
        int idx = t * CH + i;
        if (idx < NN) {
            int d = deg[idx];
            rowptr[idx] = run;
            cursor[idx] = run;
            invdeg[idx] = 1.0f / (float)(d > 0 ? d : 1);
            run += d;
        }
    }
    if (t == 1023) rowptr[NN] = run;
}

__global__ void k_scatter(const int* __restrict__ src, const int* __restrict__ dst,
                          int* __restrict__ cursor, int* __restrict__ csrsrc) {
    int e = blockIdx.x * blockDim.x + threadIdx.x;
    if (e < EE) {
        int pos = atomicAdd(&cursor[dst[e]], 1);
        csrsrc[pos] = src[e];
    }
}

// ===================== gather aggregation (R3 form) =====================
template <int D>
__global__ void k_gather(const float* __restrict__ h, float* __restrict__ out,
                         const int* __restrict__ rowptr, const int* __restrict__ csrsrc,
                         const float* __restrict__ invdeg) {
    int gw   = (blockIdx.x * blockDim.x + threadIdx.x) >> 5;
    int lane = threadIdx.x & 31;
    if (gw >= NN) return;
    int s = rowptr[gw], e = rowptr[gw + 1];
    if (D == 128) {
        float4 a0 = make_float4(0, 0, 0, 0), a1 = make_float4(0, 0, 0, 0);
        int j = s;
        for (; j + 1 < e; j += 2) {
            int s0 = csrsrc[j], s1 = csrsrc[j + 1];
            float4 v0 = *(const float4*)(h + (size_t)s0 * 128 + lane * 4);
            float4 v1 = *(const float4*)(h + (size_t)s1 * 128 + lane * 4);
            a0.x += v0.x; a0.y += v0.y; a0.z += v0.z; a0.w += v0.w;
            a1.x += v1.x; a1.y += v1.y; a1.z += v1.z; a1.w += v1.w;
        }
        if (j < e) {
            int s0 = csrsrc[j];
            float4 v0 = *(const float4*)(h + (size_t)s0 * 128 + lane * 4);
            a0.x += v0.x; a0.y += v0.y; a0.z += v0.z; a0.w += v0.w;
        }
        float iv = invdeg[gw];
        float4 r;
        r.x = (a0.x + a1.x) * iv; r.y = (a0.y + a1.y) * iv;
        r.z = (a0.z + a1.z) * iv; r.w = (a0.w + a1.w) * iv;
        *(float4*)(out + (size_t)gw * 128 + lane * 4) = r;
    } else {
        float2 a0 = make_float2(0, 0), a1 = make_float2(0, 0);
        int j = s;
        for (; j + 1 < e; j += 2) {
            int s0 = csrsrc[j], s1 = csrsrc[j + 1];
            float2 v0 = *(const float2*)(h + (size_t)s0 * 64 + lane * 2);
            float2 v1 = *(const float2*)(h + (size_t)s1 * 64 + lane * 2);
            a0.x += v0.x; a0.y += v0.y;
            a1.x += v1.x; a1.y += v1.y;
        }
        if (j < e) {
            int s0 = csrsrc[j];
            float2 v0 = *(const float2*)(h + (size_t)s0 * 64 + lane * 2);
            a0.x += v0.x; a0.y += v0.y;
        }
        float iv = invdeg[gw];
        float2 r;
        r.x = (a0.x + a1.x) * iv; r.y = (a0.y + a1.y) * iv;
        *(float2*)(out + (size_t)gw * 64 + lane * 2) = r;
    }
}

// ===================== tf32 mma dense, register-double-buffered ================
// out = [Agg|Hin]@[Wl|Wr]^T + bl ; if DO_LN: LayerNorm(gamma,beta)+ReLU fused.
// Prefetch chunk c+1's global tiles into registers while chunk c's MMAs run.
template <int DI, int DO, bool DO_LN>
__global__ __launch_bounds__(256) void k_mma(
    const float* __restrict__ Agg, const float* __restrict__ Hin,
    const float* __restrict__ Wl, const float* __restrict__ Wr,
    const float* __restrict__ bl, const float* __restrict__ gamma,
    const float* __restrict__ beta, float* __restrict__ out) {
    constexpr int WN = DO / 2;
    constexpr int NI = WN / 8;
    constexpr int NCH = 2 * DI / 32;     // total k-chunks across both phases
    constexpr int WT  = DO / 32;         // W-tile float4s per thread

    __shared__ float As[128 * ST];
    __shared__ float Ws[DO * ST];
    __shared__ float red[DO_LN ? 128 : 1][4];

    const int tid    = threadIdx.x;
    const int wid    = tid >> 5;
    const int lane   = tid & 31;
    const int g      = lane >> 2;
    const int tig    = lane & 3;
    const int warp_m = wid >> 1;
    const int warp_n = wid & 1;
    const int bm     = blockIdx.x * 128;

    float acc[2][NI][4];
    #pragma unroll
    for (int mi = 0; mi < 2; ++mi)
        #pragma unroll
        for (int ni = 0; ni < NI; ++ni)
            #pragma unroll
            for (int q = 0; q < 4; ++q) acc[mi][ni][q] = 0.f;

    float4 pa[4];
    float4 pw[WT];

    auto load_chunk = [&](int c) {
        const int ph = (c >= DI / 32) ? 1 : 0;
        const float* __restrict__ Asrc = ph ? Hin : Agg;
        const float* __restrict__ Wsrc = ph ? Wr : Wl;
        const int kl = (c - ph * (DI / 32)) * 32;
        #pragma unroll
        for (int i = 0; i < 4; ++i) {
            int flat = tid + i * 256;
            int row = flat >> 3, q = flat & 7;
            int m = bm + row;
            pa[i] = make_float4(0.f, 0.f, 0.f, 0.f);
            if (m < NN) pa[i] = *(const float4*)(Asrc + (size_t)m * DI + kl + q * 4);
        }
        #pragma unroll
        for (int i = 0; i < WT; ++i) {
            int flat = tid + i * 256;
            int row = flat >> 3, q = flat & 7;
            pw[i] = *(const float4*)(Wsrc + (size_t)row * DI + kl + q * 4);
        }
    };

    load_chunk(0);

    #pragma unroll
    for (int c = 0; c < NCH; ++c) {
        // store prefetched tiles (tf32-rounded) to smem
        #pragma unroll
        for (int i = 0; i < 4; ++i) {
            int flat = tid + i * 256;
            int row = flat >> 3, q = flat & 7;
            float4 v = pa[i];
            v.x = to_tf32(v.x); v.y = to_tf32(v.y); v.z = to_tf32(v.z); v.w = to_tf32(v.w);
            *(float4*)(As + row * ST + q * 4) = v;
        }
        #pragma unroll
        for (int i = 0; i < WT; ++i) {
            int flat = tid + i * 256;
            int row = flat >> 3, q = flat & 7;
            float4 v = pw[i];
            v.x = to_tf32(v.x); v.y = to_tf32(v.y); v.z = to_tf32(v.z); v.w = to_tf32(v.w);
            *(float4*)(Ws + row * ST + q * 4) = v;
        }
        __syncthreads();

        // prefetch next chunk while MMAs run
        if (c + 1 < NCH) load_chunk(c + 1);

        #pragma unroll
        for (int kk = 0; kk < 4; ++kk) {
            const int kb = kk * 8;
            uint32_t a[2][4];
            #pragma unroll
            for (int mi = 0; mi < 2; ++mi) {
                int rb = warp_m * 32 + mi * 16;
                a[mi][0] = __float_as_uint(As[(rb + g) * ST + kb + tig]);
                a[mi][1] = __float_as_uint(As[(rb + g + 8) * ST + kb + tig]);
                a[mi][2] = __float_as_uint(As[(rb + g) * ST + kb + tig + 4]);
                a[mi][3] = __float_as_uint(As[(rb + g + 8) * ST + kb + tig + 4]);
            }
            #pragma unroll
            for (int ni = 0; ni < NI; ++ni) {
                int nb = warp_n * WN + ni * 8;
                uint32_t b0 = __float_as_uint(Ws[(nb + g) * ST + kb + tig]);
                uint32_t b1 = __float_as_uint(Ws[(nb + g) * ST + kb + tig + 4]);
                #pragma unroll
                for (int mi = 0; mi < 2; ++mi)
                    mma_tf32(acc[mi][ni][0], acc[mi][ni][1], acc[mi][ni][2], acc[mi][ni][3],
                             a[mi][0], a[mi][1], a[mi][2], a[mi][3], b0, b1);
            }
        }
        __syncthreads();
    }

    // ---- epilogue: + bias ----
    #pragma unroll
    for (int mi = 0; mi < 2; ++mi)
        #pragma unroll
        for (int ni = 0; ni < NI; ++ni) {
            int col = warp_n * WN + ni * 8 + tig * 2;
            float b0 = bl[col], b1 = bl[col + 1];
            acc[mi][ni][0] += b0; acc[mi][ni][1] += b1;
            acc[mi][ni][2] += b0; acc[mi][ni][3] += b1;
        }

    if (DO_LN) {
        #pragma unroll
        for (int mi = 0; mi < 2; ++mi) {
            float s0 = 0.f, q0 = 0.f, s1 = 0.f, q1 = 0.f;
            #pragma unroll
            for (int ni = 0; ni < NI; ++ni) {
                s0 += acc[mi][ni][0] + acc[mi][ni][1];
                q0 += acc[mi][ni][0] * acc[mi][ni][0] + acc[mi][ni][1] * acc[mi][ni][1];
                s1 += acc[mi][ni][2] + acc[mi][ni][3];
                q1 += acc[mi][ni][2] * acc[mi][ni][2] + acc[mi][ni][3] * acc[mi][ni][3];
            }
            s0 += __shfl_xor_sync(0xFFFFFFFF, s0, 1); s0 += __shfl_xor_sync(0xFFFFFFFF, s0, 2);
            q0 += __shfl_xor_sync(0xFFFFFFFF, q0, 1); q0 += __shfl_xor_sync(0xFFFFFFFF, q0, 2);
            s1 += __shfl_xor_sync(0xFFFFFFFF, s1, 1); s1 += __shfl_xor_sync(0xFFFFFFFF, s1, 2);
            q1 += __shfl_xor_sync(0xFFFFFFFF, q1, 1); q1 += __shfl_xor_sync(0xFFFFFFFF, q1, 2);
            if (tig == 0) {
                int row0 = warp_m * 32 + mi * 16 + g;
                red[row0][warp_n * 2 + 0] = s0;
                red[row0][warp_n * 2 + 1] = q0;
                red[row0 + 8][warp_n * 2 + 0] = s1;
                red[row0 + 8][warp_n * 2 + 1] = q1;
            }
        }
        __syncthreads();
        #pragma unroll
        for (int mi = 0; mi < 2; ++mi) {
            int row0 = warp_m * 32 + mi * 16 + g;
            float sA = red[row0][0] + red[row0][2];
            float qA = red[row0][1] + red[row0][3];
            float sB = red[row0 + 8][0] + red[row0 + 8][2];
            float qB = red[row0 + 8][1] + red[row0 + 8][3];
            float m0 = sA * (1.0f / DO);
            float rs0 = rsqrtf(qA * (1.0f / DO) - m0 * m0 + LN_EPS);
            float m1 = sB * (1.0f / DO);
            float rs1 = rsqrtf(qB * (1.0f / DO) - m1 * m1 + LN_EPS);
            #pragma unroll
            for (int ni = 0; ni < NI; ++ni) {
                int col = warp_n * WN + ni * 8 + tig * 2;
                float g0 = gamma[col], g1 = gamma[col + 1];
                float bb0 = beta[col], bb1 = beta[col + 1];
                acc[mi][ni][0] = fmaxf((acc[mi][ni][0] - m0) * rs0 * g0 + bb0, 0.f);
                acc[mi][ni][1] = fmaxf((acc[mi][ni][1] - m0) * rs0 * g1 + bb1, 0.f);
                acc[mi][ni][2] = fmaxf((acc[mi][ni][2] - m1) * rs1 * g0 + bb0, 0.f);
                acc[mi][ni][3] = fmaxf((acc[mi][ni][3] - m1) * rs1 * g1 + bb1, 0.f);
            }
        }
    }

    #pragma unroll
    for (int ni = 0; ni < NI; ++ni) {
        int col = warp_n * WN + ni * 8 + tig * 2;
        #pragma unroll
        for (int mi = 0; mi < 2; ++mi) {
            int r0 = bm + warp_m * 32 + mi * 16 + g;
            if (r0 < NN)
                *(float2*)(out + (size_t)r0 * DO + col) =
                    make_float2(acc[mi][ni][0], acc[mi][ni][1]);
            int r1 = r0 + 8;
            if (r1 < NN)
                *(float2*)(out + (size_t)r1 * DO + col) =
                    make_float2(acc[mi][ni][2], acc[mi][ni][3]);
        }
    }
}

// ===================== host: forked-graph towers =====================
extern "C" void kernel_launch(void* const* d_in, const int* in_sizes, int n_in,
                              void* d_out, int out_size) {
    const float* x   = (const float*)d_in[0];
    const int*   ei  = (const int*)d_in[1];
    const int*   src = ei;
    const int*   dst = ei + EE;

    int *pDeg, *pRow, *pCur, *pCsr;
    float *pInv, *pAgg0, *pA, *pB, *pC, *pD, *pE, *pF;
    cudaGetSymbolAddress((void**)&pDeg, g_deg);
    cudaGetSymbolAddress((void**)&pRow, g_rowptr);
    cudaGetSymbolAddress((void**)&pCur, g_cursor);
    cudaGetSymbolAddress((void**)&pCsr, g_csrsrc);
    cudaGetSymbolAddress((void**)&pInv, g_invdeg);
    cudaGetSymbolAddress((void**)&pAgg0, g_agg0);
    cudaGetSymbolAddress((void**)&pA, g_bufA);
    cudaGetSymbolAddress((void**)&pB, g_bufB);
    cudaGetSymbolAddress((void**)&pC, g_bufC);
    cudaGetSymbolAddress((void**)&pD, g_bufD);
    cudaGetSymbolAddress((void**)&pE, g_bufE);
    cudaGetSymbolAddress((void**)&pF, g_bufF);

    float* h0[2] = {pA, pD};
    float* ag[2] = {pB, pE};
    float* h1[2] = {pC, pF};

    const int EB = (EE + 255) / 256;
    const int GW = (NN * 32 + 255) / 256;
    const int DB = (NN + 127) / 128;

    cudaStream_t s1;
    cudaStreamCreateWithFlags(&s1, cudaStreamNonBlocking);
    cudaEvent_t evRoot, evJoin;
    cudaEventCreateWithFlags(&evRoot, cudaEventDisableTiming);
    cudaEventCreateWithFlags(&evJoin, cudaEventDisableTiming);

    // ---- shared setup chain ----
    cudaMemsetAsync(pDeg, 0, NN * sizeof(int), 0);
    k_count<<<EB, 256>>>(dst, pDeg);
    k_scan<<<1, 1024>>>(pDeg, pRow, pCur, pInv);
    k_scatter<<<EB, 256>>>(src, dst, pCur, pCsr);
    k_gather<64><<<GW, 256>>>(x, pAgg0, pRow, pCsr, pInv);

    // ---- fork ----
    cudaEventRecord(evRoot, 0);
    cudaStreamWaitEvent(s1, evRoot, 0);

    for (int t = 0; t < 2; ++t) {
        cudaStream_t st = (t == 0) ? (cudaStream_t)0 : s1;
        const int o = 2 + t * 13;
        const float* Wl0 = (const float*)d_in[o + 0];
        const float* bl0 = (const float*)d_in[o + 1];
        const float* Wr0 = (const float*)d_in[o + 2];
        const float* g0  = (const float*)d_in[o + 3];
        const float* b0  = (const float*)d_in[o + 4];
        const float* Wl1 = (const float*)d_in[o + 5];
        const float* bl1 = (const float*)d_in[o + 6];
        const float* Wr1 = (const float*)d_in[o + 7];
        const float* g1  = (const float*)d_in[o + 8];
        const float* b1  = (const float*)d_in[o + 9];
        const float* Wl2 = (const float*)d_in[o + 10];
        const float* bl2 = (const float*)d_in[o + 11];
        const float* Wr2 = (const float*)d_in[o + 12];
        float* outT = (float*)d_out + (size_t)t * NN * 64;

        // layer 0: GEMM + fused LN+ReLU
        k_mma<64, 128, true><<<DB, 256, 0, st>>>(pAgg0, x, Wl0, Wr0, bl0, g0, b0, h0[t]);
        // layer 1
        k_gather<128><<<GW, 256, 0, st>>>(h0[t], ag[t], pRow, pCsr, pInv);
        k_mma<128, 128, true><<<DB, 256, 0, st>>>(ag[t], h0[t], Wl1, Wr1, bl1, g1, b1, h1[t]);
        // layer 2 (no LN)
        k_gather<128><<<GW, 256, 0, st>>>(h1[t], ag[t], pRow, pCsr, pInv);
        k_mma<128, 64, false><<<DB, 256, 0, st>>>(ag[t], h1[t], Wl2, Wr2, bl2,
                                                  nullptr, nullptr, outT);
    }

    // ---- join ----
    cudaEventRecord(evJoin, s1);
    cudaStreamWaitEvent((cudaStream_t)0, evJoin, 0);
}

// round 17
// speedup vs baseline: 1.0099x; 1.0055x over previous
#include <cuda_runtime.h>
#include <cuda_bf16.h>
#include <cstdint>

#define NN 50000
#define EE 800000
#define LN_EPS 1e-5f
#define ST 36

// ===================== static scratch =====================
__device__ int   g_deg[NN];
__device__ int   g_rowptr[NN + 1];
__device__ int   g_cursor[NN];
__device__ int   g_csrsrc[EE];
__device__ float g_invdeg[NN];
__device__ float g_agg0[(size_t)NN * 64];
// tower 0
__device__ float g_bufA[(size_t)NN * 128];
__device__ float g_bufB[(size_t)NN * 128];
__device__ float g_bufC[(size_t)NN * 128];
__device__ __nv_bfloat16 g_hbf0[(size_t)NN * 128];
// tower 1
__device__ float g_bufD[(size_t)NN * 128];
__device__ float g_bufE[(size_t)NN * 128];
__device__ float g_bufF[(size_t)NN * 128];
__device__ __nv_bfloat16 g_hbf1[(size_t)NN * 128];

__device__ __forceinline__ float to_tf32(float x) {
    uint32_t u;
    asm("cvt.rna.tf32.f32 %0, %1;" : "=r"(u) : "f"(x));
    return __uint_as_float(u);
}

__device__ __forceinline__ float2 bf2f(uint32_t u) {
    return __bfloat1622float2(*reinterpret_cast<const __nv_bfloat162*>(&u));
}

__device__ __forceinline__ void mma_tf32(float& d0, float& d1, float& d2, float& d3,
                                         uint32_t a0, uint32_t a1, uint32_t a2, uint32_t a3,
                                         uint32_t b0, uint32_t b1) {
    asm volatile(
        "mma.sync.aligned.m16n8k8.row.col.f32.tf32.tf32.f32 "
        "{%0,%1,%2,%3}, {%4,%5,%6,%7}, {%8,%9}, {%0,%1,%2,%3};"
        : "+f"(d0), "+f"(d1), "+f"(d2), "+f"(d3)
        : "r"(a0), "r"(a1), "r"(a2), "r"(a3), "r"(b0), "r"(b1));
}

// ===================== CSR build =====================
__global__ void k_count(const int* __restrict__ dst, int* __restrict__ deg) {
    int e = blockIdx.x * blockDim.x + threadIdx.x;
    if (e < EE) atomicAdd(&deg[dst[e]], 1);
}

__global__ void k_scan(const int* __restrict__ deg, int* __restrict__ rowptr,
                       int* __restrict__ cursor, float* __restrict__ invdeg) {
    __shared__ int sums[1024];
    const int t = threadIdx.x;
    const int CH = (NN + 1023) / 1024;
    int s = 0;
    #pragma unroll 4
    for (int i = 0; i < CH; ++i) {
        int idx = t * CH + i;
        if (idx < NN) s += deg[idx];
    }
    sums[t] = s;
    __syncthreads();
    for (int off = 1; off < 1024; off <<= 1) {
        int v = 0;
        if (t >= off) v = sums[t - off];
        __syncthreads();
        if (t >= off) sums[t] += v;
        __syncthreads();
    }
    int run = (t == 0) ? 0 : sums[t - 1];
    for (int i = 0; i < CH; ++i) {
        int idx = t * CH + i;
        if (idx < NN) {
            int d = deg[idx];
            rowptr[idx] = run;
            cursor[idx] = run;
            invdeg[idx] = 1.0f / (float)(d > 0 ? d : 1);
            run += d;
        }
    }
    if (t == 1023) rowptr[NN] = run;
}

__global__ void k_scatter(const int* __restrict__ src, const int* __restrict__ dst,
                          int* __restrict__ cursor, int* __restrict__ csrsrc) {
    int e = blockIdx.x * blockDim.x + threadIdx.x;
    if (e < EE) {
        int pos = atomicAdd(&cursor[dst[e]], 1);
        csrsrc[pos] = src[e];
    }
}

// ===================== gathers =====================
// input features (fp32, 64-wide)
__global__ void k_gather64(const float* __restrict__ h, float* __restrict__ out,
                           const int* __restrict__ rowptr, const int* __restrict__ csrsrc,
                           const float* __restrict__ invdeg) {
    int gw   = (blockIdx.x * blockDim.x + threadIdx.x) >> 5;
    int lane = threadIdx.x & 31;
    if (gw >= NN) return;
    int s = rowptr[gw], e = rowptr[gw + 1];
    float2 a0 = make_float2(0, 0), a1 = make_float2(0, 0);
    int j = s;
    for (; j + 1 < e; j += 2) {
        int s0 = csrsrc[j], s1 = csrsrc[j + 1];
        float2 v0 = *(const float2*)(h + (size_t)s0 * 64 + lane * 2);
        float2 v1 = *(const float2*)(h + (size_t)s1 * 64 + lane * 2);
        a0.x += v0.x; a0.y += v0.y;
        a1.x += v1.x; a1.y += v1.y;
    }
    if (j < e) {
        int s0 = csrsrc[j];
        float2 v0 = *(const float2*)(h + (size_t)s0 * 64 + lane * 2);
        a0.x += v0.x; a0.y += v0.y;
    }
    float iv = invdeg[gw];
    float2 r;
    r.x = (a0.x + a1.x) * iv; r.y = (a0.y + a1.y) * iv;
    *(float2*)(out + (size_t)gw * 64 + lane * 2) = r;
}

// hidden-state gather: reads bf16 rows (256B/row), accumulates fp32, writes fp32
__global__ void k_gather128bf(const __nv_bfloat16* __restrict__ hb, float* __restrict__ out,
                              const int* __restrict__ rowptr, const int* __restrict__ csrsrc,
                              const float* __restrict__ invdeg) {
    int gw   = (blockIdx.x * blockDim.x + threadIdx.x) >> 5;
    int lane = threadIdx.x & 31;
    if (gw >= NN) return;
    int s = rowptr[gw], e = rowptr[gw + 1];
    float4 a0 = make_float4(0, 0, 0, 0), a1 = make_float4(0, 0, 0, 0);
    int j = s;
    for (; j + 1 < e; j += 2) {
        int s0 = csrsrc[j], s1 = csrsrc[j + 1];
        uint2 u0 = *(const uint2*)(hb + (size_t)s0 * 128 + lane * 4);
        uint2 u1 = *(const uint2*)(hb + (size_t)s1 * 128 + lane * 4);
        float2 f0 = bf2f(u0.x), f1 = bf2f(u0.y);
        float2 f2 = bf2f(u1.x), f3 = bf2f(u1.y);
        a0.x += f0.x; a0.y += f0.y; a0.z += f1.x; a0.w += f1.y;
        a1.x += f2.x; a1.y += f2.y; a1.z += f3.x; a1.w += f3.y;
    }
    if (j < e) {
        int s0 = csrsrc[j];
        uint2 u0 = *(const uint2*)(hb + (size_t)s0 * 128 + lane * 4);
        float2 f0 = bf2f(u0.x), f1 = bf2f(u0.y);
        a0.x += f0.x; a0.y += f0.y; a0.z += f1.x; a0.w += f1.y;
    }
    float iv = invdeg[gw];
    float4 r;
    r.x = (a0.x + a1.x) * iv; r.y = (a0.y + a1.y) * iv;
    r.z = (a0.z + a1.z) * iv; r.w = (a0.w + a1.w) * iv;
    *(float4*)(out + (size_t)gw * 128 + lane * 4) = r;
}

// ===================== tf32 mma dense, reg-double-buffered + fused LN + bf16 out ==
// out = [Agg|Hin]@[Wl|Wr]^T + bl ; if DO_LN: LN(gamma,beta)+ReLU fused, and
// a bf16 copy of the result is written to outbf (for the next gather pass).
template <int DI, int DO, bool DO_LN>
__global__ __launch_bounds__(256) void k_mma(
    const float* __restrict__ Agg, const float* __restrict__ Hin,
    const float* __restrict__ Wl, const float* __restrict__ Wr,
    const float* __restrict__ bl, const float* __restrict__ gamma,
    const float* __restrict__ beta, float* __restrict__ out,
    __nv_bfloat16* __restrict__ outbf) {
    constexpr int WN = DO / 2;
    constexpr int NI = WN / 8;
    constexpr int NCH = 2 * DI / 32;
    constexpr int WT  = DO / 32;

    __shared__ float As[128 * ST];
    __shared__ float Ws[DO * ST];
    __shared__ float red[DO_LN ? 128 : 1][4];

    const int tid    = threadIdx.x;
    const int wid    = tid >> 5;
    const int lane   = tid & 31;
    const int g      = lane >> 2;
    const int tig    = lane & 3;
    const int warp_m = wid >> 1;
    const int warp_n = wid & 1;
    const int bm     = blockIdx.x * 128;

    float acc[2][NI][4];
    #pragma unroll
    for (int mi = 0; mi < 2; ++mi)
        #pragma unroll
        for (int ni = 0; ni < NI; ++ni)
            #pragma unroll
            for (int q = 0; q < 4; ++q) acc[mi][ni][q] = 0.f;

    float4 pa[4];
    float4 pw[WT];

    auto load_chunk = [&](int c) {
        const int ph = (c >= DI / 32) ? 1 : 0;
        const float* __restrict__ Asrc = ph ? Hin : Agg;
        const float* __restrict__ Wsrc = ph ? Wr : Wl;
        const int kl = (c - ph * (DI / 32)) * 32;
        #pragma unroll
        for (int i = 0; i < 4; ++i) {
            int flat = tid + i * 256;
            int row = flat >> 3, q = flat & 7;
            int m = bm + row;
            pa[i] = make_float4(0.f, 0.f, 0.f, 0.f);
            if (m < NN) pa[i] = *(const float4*)(Asrc + (size_t)m * DI + kl + q * 4);
        }
        #pragma unroll
        for (int i = 0; i < WT; ++i) {
            int flat = tid + i * 256;
            int row = flat >> 3, q = flat & 7;
            pw[i] = *(const float4*)(Wsrc + (size_t)row * DI + kl + q * 4);
        }
    };

    load_chunk(0);

    #pragma unroll
    for (int c = 0; c < NCH; ++c) {
        #pragma unroll
        for (int i = 0; i < 4; ++i) {
            int flat = tid + i * 256;
            int row = flat >> 3, q = flat & 7;
            float4 v = pa[i];
            v.x = to_tf32(v.x); v.y = to_tf32(v.y); v.z = to_tf32(v.z); v.w = to_tf32(v.w);
            *(float4*)(As + row * ST + q * 4) = v;
        }
        #pragma unroll
        for (int i = 0; i < WT; ++i) {
            int flat = tid + i * 256;
            int row = flat >> 3, q = flat & 7;
            float4 v = pw[i];
            v.x = to_tf32(v.x); v.y = to_tf32(v.y); v.z = to_tf32(v.z); v.w = to_tf32(v.w);
            *(float4*)(Ws + row * ST + q * 4) = v;
        }
        __syncthreads();

        if (c + 1 < NCH) load_chunk(c + 1);

        #pragma unroll
        for (int kk = 0; kk < 4; ++kk) {
            const int kb = kk * 8;
            uint32_t a[2][4];
            #pragma unroll
            for (int mi = 0; mi < 2; ++mi) {
                int rb = warp_m * 32 + mi * 16;
                a[mi][0] = __float_as_uint(As[(rb + g) * ST + kb + tig]);
                a[mi][1] = __float_as_uint(As[(rb + g + 8) * ST + kb + tig]);
                a[mi][2] = __float_as_uint(As[(rb + g) * ST + kb + tig + 4]);
                a[mi][3] = __float_as_uint(As[(rb + g + 8) * ST + kb + tig + 4]);
            }
            #pragma unroll
            for (int ni = 0; ni < NI; ++ni) {
                int nb = warp_n * WN + ni * 8;
                uint32_t b0 = __float_as_uint(Ws[(nb + g) * ST + kb + tig]);
                uint32_t b1 = __float_as_uint(Ws[(nb + g) * ST + kb + tig + 4]);
                #pragma unroll
                for (int mi = 0; mi < 2; ++mi)
                    mma_tf32(acc[mi][ni][0], acc[mi][ni][1], acc[mi][ni][2], acc[mi][ni][3],
                             a[mi][0], a[mi][1], a[mi][2], a[mi][3], b0, b1);
            }
        }
        __syncthreads();
    }

    // ---- epilogue: + bias ----
    #pragma unroll
    for (int mi = 0; mi < 2; ++mi)
        #pragma unroll
        for (int ni = 0; ni < NI; ++ni) {
            int col = warp_n * WN + ni * 8 + tig * 2;
            float b0 = bl[col], b1 = bl[col + 1];
            acc[mi][ni][0] += b0; acc[mi][ni][1] += b1;
            acc[mi][ni][2] += b0; acc[mi][ni][3] += b1;
        }

    if (DO_LN) {
        #pragma unroll
        for (int mi = 0; mi < 2; ++mi) {
            float s0 = 0.f, q0 = 0.f, s1 = 0.f, q1 = 0.f;
            #pragma unroll
            for (int ni = 0; ni < NI; ++ni) {
                s0 += acc[mi][ni][0] + acc[mi][ni][1];
                q0 += acc[mi][ni][0] * acc[mi][ni][0] + acc[mi][ni][1] * acc[mi][ni][1];
                s1 += acc[mi][ni][2] + acc[mi][ni][3];
                q1 += acc[mi][ni][2] * acc[mi][ni][2] + acc[mi][ni][3] * acc[mi][ni][3];
            }
            s0 += __shfl_xor_sync(0xFFFFFFFF, s0, 1); s0 += __shfl_xor_sync(0xFFFFFFFF, s0, 2);
            q0 += __shfl_xor_sync(0xFFFFFFFF, q0, 1); q0 += __shfl_xor_sync(0xFFFFFFFF, q0, 2);
            s1 += __shfl_xor_sync(0xFFFFFFFF, s1, 1); s1 += __shfl_xor_sync(0xFFFFFFFF, s1, 2);
            q1 += __shfl_xor_sync(0xFFFFFFFF, q1, 1); q1 += __shfl_xor_sync(0xFFFFFFFF, q1, 2);
            if (tig == 0) {
                int row0 = warp_m * 32 + mi * 16 + g;
                red[row0][warp_n * 2 + 0] = s0;
                red[row0][warp_n * 2 + 1] = q0;
                red[row0 + 8][warp_n * 2 + 0] = s1;
                red[row0 + 8][warp_n * 2 + 1] = q1;
            }
        }
        __syncthreads();
        #pragma unroll
        for (int mi = 0; mi < 2; ++mi) {
            int row0 = warp_m * 32 + mi * 16 + g;
            float sA = red[row0][0] + red[row0][2];
            float qA = red[row0][1] + red[row0][3];
            float sB = red[row0 + 8][0] + red[row0 + 8][2];
            float qB = red[row0 + 8][1] + red[row0 + 8][3];
            float m0 = sA * (1.0f / DO);
            float rs0 = rsqrtf(qA * (1.0f / DO) - m0 * m0 + LN_EPS);
            float m1 = sB * (1.0f / DO);
            float rs1 = rsqrtf(qB * (1.0f / DO) - m1 * m1 + LN_EPS);
            #pragma unroll
            for (int ni = 0; ni < NI; ++ni) {
                int col = warp_n * WN + ni * 8 + tig * 2;
                float g0 = gamma[col], g1 = gamma[col + 1];
                float bb0 = beta[col], bb1 = beta[col + 1];
                acc[mi][ni][0] = fmaxf((acc[mi][ni][0] - m0) * rs0 * g0 + bb0, 0.f);
                acc[mi][ni][1] = fmaxf((acc[mi][ni][1] - m0) * rs0 * g1 + bb1, 0.f);
                acc[mi][ni][2] = fmaxf((acc[mi][ni][2] - m1) * rs1 * g0 + bb0, 0.f);
                acc[mi][ni][3] = fmaxf((acc[mi][ni][3] - m1) * rs1 * g1 + bb1, 0.f);
            }
        }
    }

    #pragma unroll
    for (int ni = 0; ni < NI; ++ni) {
        int col = warp_n * WN + ni * 8 + tig * 2;
        #pragma unroll
        for (int mi = 0; mi < 2; ++mi) {
            int r0 = bm + warp_m * 32 + mi * 16 + g;
            if (r0 < NN) {
                *(float2*)(out + (size_t)r0 * DO + col) =
                    make_float2(acc[mi][ni][0], acc[mi][ni][1]);
                if (DO_LN) {
                    __nv_bfloat162 p = __floats2bfloat162_rn(acc[mi][ni][0], acc[mi][ni][1]);
                    *(uint32_t*)(outbf + (size_t)r0 * DO + col) =
                        *reinterpret_cast<uint32_t*>(&p);
                }
            }
            int r1 = r0 + 8;
            if (r1 < NN) {
                *(float2*)(out + (size_t)r1 * DO + col) =
                    make_float2(acc[mi][ni][2], acc[mi][ni][3]);
                if (DO_LN) {
                    __nv_bfloat162 p = __floats2bfloat162_rn(acc[mi][ni][2], acc[mi][ni][3]);
                    *(uint32_t*)(outbf + (size_t)r1 * DO + col) =
                        *reinterpret_cast<uint32_t*>(&p);
                }
            }
        }
    }
}

// ===================== host: forked-graph towers =====================
extern "C" void kernel_launch(void* const* d_in, const int* in_sizes, int n_in,
                              void* d_out, int out_size) {
    const float* x   = (const float*)d_in[0];
    const int*   ei  = (const int*)d_in[1];
    const int*   src = ei;
    const int*   dst = ei + EE;

    int *pDeg, *pRow, *pCur, *pCsr;
    float *pInv, *pAgg0, *pA, *pB, *pC, *pD, *pE, *pF;
    __nv_bfloat16 *pBf0, *pBf1;
    cudaGetSymbolAddress((void**)&pDeg, g_deg);
    cudaGetSymbolAddress((void**)&pRow, g_rowptr);
    cudaGetSymbolAddress((void**)&pCur, g_cursor);
    cudaGetSymbolAddress((void**)&pCsr, g_csrsrc);
    cudaGetSymbolAddress((void**)&pInv, g_invdeg);
    cudaGetSymbolAddress((void**)&pAgg0, g_agg0);
    cudaGetSymbolAddress((void**)&pA, g_bufA);
    cudaGetSymbolAddress((void**)&pB, g_bufB);
    cudaGetSymbolAddress((void**)&pC, g_bufC);
    cudaGetSymbolAddress((void**)&pD, g_bufD);
    cudaGetSymbolAddress((void**)&pE, g_bufE);
    cudaGetSymbolAddress((void**)&pF, g_bufF);
    cudaGetSymbolAddress((void**)&pBf0, g_hbf0);
    cudaGetSymbolAddress((void**)&pBf1, g_hbf1);

    float* h0[2] = {pA, pD};
    float* ag[2] = {pB, pE};
    float* h1[2] = {pC, pF};
    __nv_bfloat16* hbf[2] = {pBf0, pBf1};

    const int EB = (EE + 255) / 256;
    const int GW = (NN * 32 + 255) / 256;
    const int DB = (NN + 127) / 128;

    cudaStream_t s1;
    cudaStreamCreateWithFlags(&s1, cudaStreamNonBlocking);
    cudaEvent_t evRoot, evJoin;
    cudaEventCreateWithFlags(&evRoot, cudaEventDisableTiming);
    cudaEventCreateWithFlags(&evJoin, cudaEventDisableTiming);

    // ---- shared setup chain ----
    cudaMemsetAsync(pDeg, 0, NN * sizeof(int), 0);
    k_count<<<EB, 256>>>(dst, pDeg);
    k_scan<<<1, 1024>>>(pDeg, pRow, pCur, pInv);
    k_scatter<<<EB, 256>>>(src, dst, pCur, pCsr);
    k_gather64<<<GW, 256>>>(x, pAgg0, pRow, pCsr, pInv);

    // ---- fork ----
    cudaEventRecord(evRoot, 0);
    cudaStreamWaitEvent(s1, evRoot, 0);

    for (int t = 0; t < 2; ++t) {
        cudaStream_t st = (t == 0) ? (cudaStream_t)0 : s1;
        const int o = 2 + t * 13;
        const float* Wl0 = (const float*)d_in[o + 0];
        const float* bl0 = (const float*)d_in[o + 1];
        const float* Wr0 = (const float*)d_in[o + 2];
        const float* g0  = (const float*)d_in[o + 3];
        const float* b0  = (const float*)d_in[o + 4];
        const float* Wl1 = (const float*)d_in[o + 5];
        const float* bl1 = (const float*)d_in[o + 6];
        const float* Wr1 = (const float*)d_in[o + 7];
        const float* g1  = (const float*)d_in[o + 8];
        const float* b1  = (const float*)d_in[o + 9];
        const float* Wl2 = (const float*)d_in[o + 10];
        const float* bl2 = (const float*)d_in[o + 11];
        const float* Wr2 = (const float*)d_in[o + 12];
        float* outT = (float*)d_out + (size_t)t * NN * 64;

        // layer 0: GEMM + fused LN+ReLU (+ bf16 copy for the gather)
        k_mma<64, 128, true><<<DB, 256, 0, st>>>(pAgg0, x, Wl0, Wr0, bl0, g0, b0,
                                                 h0[t], hbf[t]);
        // layer 1: bf16 gather
        k_gather128bf<<<GW, 256, 0, st>>>(hbf[t], ag[t], pRow, pCsr, pInv);
        k_mma<128, 128, true><<<DB, 256, 0, st>>>(ag[t], h0[t], Wl1, Wr1, bl1, g1, b1,
                                                  h1[t], hbf[t]);
        // layer 2: bf16 gather, GEMM (no LN) -> d_out
        k_gather128bf<<<GW, 256, 0, st>>>(hbf[t], ag[t], pRow, pCsr, pInv);
        k_mma<128, 64, false><<<DB, 256, 0, st>>>(ag[t], h1[t], Wl2, Wr2, bl2,
                                                  nullptr, nullptr, outT, nullptr);
    }

    // ---- join ----
    cudaEventRecord(evJoin, s1);
    cudaStreamWaitEvent((cudaStream_t)0, evJoin, 0);
}